// round 4
// baseline (speedup 1.0000x reference)
#include <cuda_runtime.h>
#include <cuda_bf16.h>
#include <math_constants.h>

// ---------------------------------------------------------------------------
// GCNLayer_V2: trimmed-mean neighbor aggregation + linear + bias + relu
//
// Inputs (metadata order):
//   d_in[0] h      float [20000,128]
//   d_in[1] norm   float [20000,1]
//   d_in[2] weight float [128,128]
//   d_in[3] bias   float [128]
//   d_in[4] nbr    int32 [20000,32]
//   d_in[5] deg    int32 [20000]
// Output: float [20000,128] = relu(accum @ W + b)
// ---------------------------------------------------------------------------

#define NNODE 20000
#define FDIM 128
#define DMAX 32

typedef unsigned long long ull;

// scratch for the aggregated features (device global: no allocation allowed)
__device__ float g_accum[NNODE * FDIM];

// ---------------------------------------------------------------------------
// Compile-time trim bound. Matches runtime floorf(__fmul_rn(n,0.45f)):
// single-rounded IEEE fp32 multiply, truncation == floor for positives.
// ---------------------------------------------------------------------------
__host__ __device__ constexpr int trim_b(int n) {
    int braw = n / 2 - (1 - (n & 1));
    int bcap = (int)((float)n * 0.45f);
    int b = braw < bcap ? braw : bcap;
    return b < 1 ? 1 : b;
}
__host__ __device__ constexpr int next_pow2c(int n) {
    int p = 1;
    while (p < n) p <<= 1;
    return p;
}

// ---------------------------------------------------------------------------
// Batcher odd-even merge sort network (pow2), generated at compile time.
// ---------------------------------------------------------------------------
template <int S>
struct OEMSNet {
    int a[200];
    int b[200];
    int count;

    __host__ __device__ constexpr void cmp(int i, int j) {
        a[count] = i; b[count] = j; ++count;
    }

    __host__ __device__ constexpr void merge(int lo, int n, int r) {
        int m = r * 2;
        if (m < n) {
            merge(lo, n, m);
            merge(lo + r, n, m);
            for (int i = lo + r; i + r < lo + n; i += m) cmp(i, i + r);
        } else {
            cmp(lo, lo + r);
        }
    }

    __host__ __device__ constexpr void sort(int lo, int n) {
        if (n > 1) {
            int m = n / 2;
            sort(lo, m);
            sort(lo + m, m);
            merge(lo, n, 1);
        }
    }

    __host__ __device__ constexpr OEMSNet() : a(), b(), count(0) { sort(0, S); }
};

// ---------------------------------------------------------------------------
// Pruned network for exact size N and output window [LO, HI):
//  1. build OEMS on next pow2; drop CEs with high index >= N (sentinel no-ops:
//     slots >= N provably hold +inf throughout, min always lands low).
//  2. backward liveness pruning: keep a CE iff it transitively feeds a wire
//     in [LO, HI).
// ---------------------------------------------------------------------------
template <int N, int LO, int HI>
struct PrunedNet {
    int a[200];
    int b[200];
    int count;

    __host__ __device__ constexpr PrunedNet() : a(), b(), count(0) {
        constexpr int P = next_pow2c(N);
        OEMSNet<P> full{};

        int ta[200] = {};
        int tb[200] = {};
        int tc = 0;
        for (int p = 0; p < full.count; ++p)
            if (full.b[p] < N) { ta[tc] = full.a[p]; tb[tc] = full.b[p]; ++tc; }

        bool live[64] = {};
        for (int i = LO; i < HI; ++i) live[i] = true;
        bool keep[200] = {};
        for (int p = tc - 1; p >= 0; --p) {
            if (live[ta[p]] || live[tb[p]]) {
                keep[p] = true;
                live[ta[p]] = true;
                live[tb[p]] = true;
            }
        }
        for (int p = 0; p < tc; ++p)
            if (keep[p]) { a[count] = ta[p]; b[count] = tb[p]; ++count; }
    }
};

// ---------------------------------------------------------------------------
// Kernel 1: per-node, per-feature trimmed aggregation.
// Block = 128 threads (one per feature), grid = N nodes. deg is block-uniform
// so the exact-N dispatch is branch-coherent. Each thread sorts (key = h,
// val = h*norm) pairs through the pruned network; window sum is LO..HI-1.
// Float keys: ties only occur for duplicate src indices -> identical
// payloads -> tie order never affects the sum.
// ---------------------------------------------------------------------------

template <int N>
__device__ __forceinline__ float trimmed(const float* __restrict__ h,
                                         const int* s_nbr,
                                         const float* s_norm,
                                         int tid, float self0, float normd) {
    constexpr int B = trim_b(N);
    constexpr int LO = B;
    constexpr int HI = N - B;

    float key[N];
    float val[N];
#pragma unroll
    for (int d = 0; d < N; ++d) {
        int src = s_nbr[d];
        float x = __ldg(&h[src * FDIM + tid]);
        key[d] = x;
        val[d] = x * s_norm[d];
    }

    constexpr PrunedNet<N, LO, HI> net{};
#pragma unroll
    for (int p = 0; p < net.count; ++p) {
        const int i = net.a[p];
        const int l = net.b[p];
        float ki = key[i], kl = key[l];
        bool sw = ki > kl;
        key[i] = fminf(ki, kl);       // FMNMX: no predicate dependency
        key[l] = fmaxf(ki, kl);
        float vi = val[i], vl = val[l];
        val[i] = sw ? vl : vi;
        val[l] = sw ? vi : vl;
    }

    float ts = 0.0f;
#pragma unroll
    for (int r = LO; r < HI; ++r) ts += val[r];

    return (ts + self0 * (float)(2 * B)) * normd;
}

__global__ __launch_bounds__(FDIM)
void agg_kernel(const float* __restrict__ h,
                const float* __restrict__ norm,
                const int* __restrict__ nbr,
                const int* __restrict__ deg,
                int nnode) {
    int node = blockIdx.x;
    if (node >= nnode) return;
    int tid = threadIdx.x;

    __shared__ int s_nbr[DMAX];
    __shared__ float s_norm[DMAX];
    __shared__ int s_n;
    __shared__ float s_nd;

    if (tid < DMAX) {
        int src = nbr[node * DMAX + tid];
        s_nbr[tid] = src;
        s_norm[tid] = norm[src];
    }
    if (tid == 0) {
        s_n = deg[node];
        s_nd = norm[node];
    }
    __syncthreads();

    int n = s_n;                 // block-uniform
    float normd = s_nd;
    float self0 = h[node * FDIM + tid] * normd;

    float acc = 0.0f;
    if (n <= 3) {
        acc = ((float)n * self0) * normd;
    } else {
#define AGG_CASE(NN) case NN: acc = trimmed<NN>(h, s_nbr, s_norm, tid, self0, normd); break;
        switch (n) {
            AGG_CASE(4)  AGG_CASE(5)  AGG_CASE(6)  AGG_CASE(7)
            AGG_CASE(8)  AGG_CASE(9)  AGG_CASE(10) AGG_CASE(11)
            AGG_CASE(12) AGG_CASE(13) AGG_CASE(14) AGG_CASE(15)
            AGG_CASE(16) AGG_CASE(17) AGG_CASE(18) AGG_CASE(19)
            AGG_CASE(20) AGG_CASE(21) AGG_CASE(22) AGG_CASE(23)
            AGG_CASE(24) AGG_CASE(25) AGG_CASE(26) AGG_CASE(27)
            AGG_CASE(28) AGG_CASE(29) AGG_CASE(30) AGG_CASE(31)
            AGG_CASE(32)
            default: break;
        }
#undef AGG_CASE
    }
    g_accum[node * FDIM + tid] = acc;
}

// ---------------------------------------------------------------------------
// Kernel 2: out = relu(accum @ W + bias)
// Block = 128 threads, tile = 64 rows x 128 cols; 8x8 register tile per
// thread, f32x2-packed accumulators over column pairs, fma.rn.f32x2 inner
// product. W in 64KB dynamic smem -> 3 blocks/SM (12 warps) so the fma pipe,
// not latency, binds. A is read straight from global: within a warp only 2
// distinct addresses per load (16-way broadcast), served by L1.
// ---------------------------------------------------------------------------

#define GT_ROWS 64
#define GEMM_SMEM_BYTES (FDIM * FDIM * 4)   // 64 KB

__device__ __forceinline__ void fma2(ull& d, ull a, ull b) {
    asm("fma.rn.f32x2 %0, %1, %2, %0;" : "+l"(d) : "l"(a), "l"(b));
}
__device__ __forceinline__ ull dup2(float x) {
    ull r;
    asm("mov.b64 %0, {%1, %1};" : "=l"(r) : "f"(x));
    return r;
}
__device__ __forceinline__ void unpack2(float& lo, float& hi, ull v) {
    asm("mov.b64 {%0, %1}, %2;" : "=f"(lo), "=f"(hi) : "l"(v));
}

__global__ __launch_bounds__(128, 3)
void gemm_kernel(const float* __restrict__ W,
                 const float* __restrict__ bias,
                 float* __restrict__ out,
                 int nnode) {
    extern __shared__ float Ws[];      // [128][128], same layout as W

    int tid = threadIdx.x;
    int row0 = blockIdx.x * GT_ROWS;

    // stage W (coalesced float4)
    {
        const float4* Wg = reinterpret_cast<const float4*>(W);
        float4* Wsm = reinterpret_cast<float4*>(Ws);
#pragma unroll
        for (int i = 0; i < FDIM * FDIM / 4 / 128; ++i)
            Wsm[tid + i * 128] = Wg[tid + i * 128];
    }
    __syncthreads();

    int tx = tid & 15;       // column group: cols tx*8 .. tx*8+7
    int ty = tid >> 4;       // row group:    rows ty*8 .. ty*8+7

    ull acc[32];             // acc[r*4+c2] = (row ty*8+r, cols tx*8+2c2..+1)
#pragma unroll
    for (int i = 0; i < 32; ++i) acc[i] = 0ull;

    // per-row A base pointers (clamped for the tail block)
    const float* arow[8];
#pragma unroll
    for (int r = 0; r < 8; ++r) {
        int row = row0 + ty * 8 + r;
        row = row < nnode ? row : nnode - 1;
        arow[r] = g_accum + row * FDIM;
    }

    const ull* wbase = reinterpret_cast<const ull*>(Ws + tx * 8);

#pragma unroll 4
    for (int f2 = 0; f2 < FDIM / 2; ++f2) {
        // A: two f-values per row as one 8B broadcast load
        float2 av[8];
#pragma unroll
        for (int r = 0; r < 8; ++r)
            av[r] = __ldg(reinterpret_cast<const float2*>(arow[r]) + f2);

        // W: column pairs for f and f+1
        ull w0[4], w1[4];
        const ull* wp0 = wbase + (2 * f2) * (FDIM / 2);
        const ull* wp1 = wp0 + (FDIM / 2);
#pragma unroll
        for (int c2 = 0; c2 < 4; ++c2) { w0[c2] = wp0[c2]; w1[c2] = wp1[c2]; }

#pragma unroll
        for (int r = 0; r < 8; ++r) {
            ull a0 = dup2(av[r].x);
            ull a1 = dup2(av[r].y);
#pragma unroll
            for (int c2 = 0; c2 < 4; ++c2) {
                fma2(acc[r * 4 + c2], a0, w0[c2]);
                fma2(acc[r * 4 + c2], a1, w1[c2]);
            }
        }
    }

    // epilogue: bias + relu + store
    float bcol[8];
#pragma unroll
    for (int c = 0; c < 8; ++c) bcol[c] = __ldg(&bias[tx * 8 + c]);

#pragma unroll
    for (int r = 0; r < 8; ++r) {
        int row = row0 + ty * 8 + r;
        if (row < nnode) {
            float* orow = out + row * FDIM + tx * 8;
#pragma unroll
            for (int c2 = 0; c2 < 4; ++c2) {
                float lo, hi;
                unpack2(lo, hi, acc[r * 4 + c2]);
                float2 o;
                o.x = fmaxf(lo + bcol[2 * c2], 0.0f);
                o.y = fmaxf(hi + bcol[2 * c2 + 1], 0.0f);
                *reinterpret_cast<float2*>(orow + 2 * c2) = o;
            }
        }
    }
}

// ---------------------------------------------------------------------------
// launch
// ---------------------------------------------------------------------------

extern "C" void kernel_launch(void* const* d_in, const int* in_sizes, int n_in,
                              void* d_out, int out_size) {
    const float* h    = (const float*)d_in[0];
    const float* norm = (const float*)d_in[1];
    const float* W    = (const float*)d_in[2];
    const float* bias = (const float*)d_in[3];
    const int*   nbr  = (const int*)d_in[4];
    const int*   deg  = (const int*)d_in[5];
    float* out = (float*)d_out;

    int nnode = in_sizes[5];   // 20000

    cudaFuncSetAttribute(gemm_kernel,
                         cudaFuncAttributeMaxDynamicSharedMemorySize,
                         GEMM_SMEM_BYTES);

    agg_kernel<<<nnode, FDIM>>>(h, norm, nbr, deg, nnode);

    int gemm_blocks = (nnode + GT_ROWS - 1) / GT_ROWS;   // 313
    gemm_kernel<<<gemm_blocks, 128, GEMM_SMEM_BYTES>>>(W, bias, out, nnode);
}

// round 5
// speedup vs baseline: 1.6638x; 1.6638x over previous
#include <cuda_runtime.h>
#include <cuda_bf16.h>
#include <math_constants.h>

// ---------------------------------------------------------------------------
// GCNLayer_V2: trimmed-mean neighbor aggregation + linear + bias + relu
//
// Inputs (metadata order):
//   d_in[0] h      float [20000,128]
//   d_in[1] norm   float [20000,1]
//   d_in[2] weight float [128,128]
//   d_in[3] bias   float [128]
//   d_in[4] nbr    int32 [20000,32]
//   d_in[5] deg    int32 [20000]
// Output: float [20000,128] = relu(accum @ W + b)
// ---------------------------------------------------------------------------

#define NNODE 20000
#define FDIM 128
#define DMAX 32

typedef unsigned long long ull;

// scratch for the aggregated features (device global: no allocation allowed)
__device__ float g_accum[NNODE * FDIM];

// ---------------------------------------------------------------------------
// Compile-time trim bound. Matches runtime floorf(__fmul_rn(n,0.45f)).
// ---------------------------------------------------------------------------
__host__ __device__ constexpr int trim_b(int n) {
    int braw = n / 2 - (1 - (n & 1));
    int bcap = (int)((float)n * 0.45f);
    int b = braw < bcap ? braw : bcap;
    return b < 1 ? 1 : b;
}
// union trim-window over a degree range (for per-class network pruning)
__host__ __device__ constexpr int union_lo(int nmin, int nmax) {
    int m = 1 << 30;
    for (int n = nmin; n <= nmax; ++n) { int v = trim_b(n); if (v < m) m = v; }
    return m;
}
__host__ __device__ constexpr int union_hi(int nmin, int nmax) {
    int M = 0;
    for (int n = nmin; n <= nmax; ++n) { int v = n - trim_b(n); if (v > M) M = v; }
    return M;
}

// ---------------------------------------------------------------------------
// Batcher odd-even merge sort network (pow2), generated at compile time.
// ---------------------------------------------------------------------------
template <int S>
struct OEMSNet {
    int a[200];
    int b[200];
    int count;

    __host__ __device__ constexpr void cmp(int i, int j) {
        a[count] = i; b[count] = j; ++count;
    }
    __host__ __device__ constexpr void merge(int lo, int n, int r) {
        int m = r * 2;
        if (m < n) {
            merge(lo, n, m);
            merge(lo + r, n, m);
            for (int i = lo + r; i + r < lo + n; i += m) cmp(i, i + r);
        } else {
            cmp(lo, lo + r);
        }
    }
    __host__ __device__ constexpr void sort(int lo, int n) {
        if (n > 1) {
            int m = n / 2;
            sort(lo, m);
            sort(lo + m, m);
            merge(lo, n, 1);
        }
    }
    __host__ __device__ constexpr OEMSNet() : a(), b(), count(0) { sort(0, S); }
};

// ---------------------------------------------------------------------------
// Class network: full OEMS<S> pruned by backward liveness so that only CEs
// transitively feeding the union window [ULO, UHI) survive. Valid for any
// runtime n <= S (padded slots hold +inf sentinels; they are ordinary wires).
// ---------------------------------------------------------------------------
template <int S, int ULO, int UHI>
struct ClassNet {
    int a[200];
    int b[200];
    int count;

    __host__ __device__ constexpr ClassNet() : a(), b(), count(0) {
        OEMSNet<S> full{};
        bool live[64] = {};
        for (int i = ULO; i < UHI; ++i) live[i] = true;
        bool keep[200] = {};
        for (int p = full.count - 1; p >= 0; --p) {
            if (live[full.a[p]] || live[full.b[p]]) {
                keep[p] = true;
                live[full.a[p]] = true;
                live[full.b[p]] = true;
            }
        }
        for (int p = 0; p < full.count; ++p)
            if (keep[p]) { a[count] = full.a[p]; b[count] = full.b[p]; ++count; }
    }
};

// ---------------------------------------------------------------------------
// Kernel 1: per-node, per-feature trimmed aggregation.
// Block = 128 threads (one per feature), grid = N nodes. deg is block-uniform
// so the 3-class dispatch is branch-coherent; 3 instantiations keep the hot
// code inside L1.5-I$ (the 29-variant version thrashed I$). Each thread sorts
// (key = h, val = h*norm) pairs through the window-pruned network and does a
// masked sum over the union window only.
// ---------------------------------------------------------------------------

template <int S, int NMIN, int NMAX>
__device__ __forceinline__ float trimmed_cls(const float* __restrict__ h,
                                             const int* s_nbr,
                                             const float* s_norm,
                                             int n, int lo, int hi, int tid) {
    constexpr int ULO = union_lo(NMIN, NMAX);
    constexpr int UHI = union_hi(NMIN, NMAX);

    float key[S];
    float val[S];
#pragma unroll
    for (int d = 0; d < S; ++d) {
        if (d < n) {
            int src = s_nbr[d];
            float x = __ldg(&h[src * FDIM + tid]);
            key[d] = x;
            val[d] = x * s_norm[d];
        } else {
            key[d] = CUDART_INF_F;   // sentinel: sorts past all valid
            val[d] = 0.0f;
        }
    }

    constexpr ClassNet<S, ULO, UHI> net{};
#pragma unroll
    for (int p = 0; p < net.count; ++p) {
        const int i = net.a[p];
        const int l = net.b[p];
        float ki = key[i], kl = key[l];
        bool sw = ki > kl;
        key[i] = fminf(ki, kl);       // FMNMX: no predicate dependency
        key[l] = fmaxf(ki, kl);
        float vi = val[i], vl = val[l];
        val[i] = sw ? vl : vi;
        val[l] = sw ? vi : vl;
    }

    // masked sum over the (narrow) union window, ascending rank order
    float ts = 0.0f;
#pragma unroll
    for (int r = ULO; r < UHI; ++r) {
        bool sel = (r >= lo) && (r < hi);
        ts += sel ? val[r] : 0.0f;
    }
    return ts;
}

__global__ __launch_bounds__(FDIM)
void agg_kernel(const float* __restrict__ h,
                const float* __restrict__ norm,
                const int* __restrict__ nbr,
                const int* __restrict__ deg,
                int nnode) {
    int node = blockIdx.x;
    if (node >= nnode) return;
    int tid = threadIdx.x;

    __shared__ int s_nbr[DMAX];
    __shared__ float s_norm[DMAX];
    __shared__ int s_n;
    __shared__ float s_nd;

    if (tid < DMAX) {
        int src = nbr[node * DMAX + tid];
        s_nbr[tid] = src;
        s_norm[tid] = norm[src];
    }
    if (tid == 0) {
        s_n = deg[node];
        s_nd = norm[node];
    }
    __syncthreads();

    int n = s_n;                 // block-uniform
    float normd = s_nd;
    float self0 = h[node * FDIM + tid] * normd;

    float acc;
    if (n <= 3) {
        acc = ((float)n * self0) * normd;
    } else {
        int braw = (n >> 1) - (1 - (n & 1));
        int bcap = (int)floorf(__fmul_rn((float)n, 0.45f));
        int b = min(braw, bcap);
        b = max(b, 1);
        int lo = b, hi = n - b;

        float ts;
        if (n <= 8)
            ts = trimmed_cls<8, 4, 8>(h, s_nbr, s_norm, n, lo, hi, tid);
        else if (n <= 16)
            ts = trimmed_cls<16, 9, 16>(h, s_nbr, s_norm, n, lo, hi, tid);
        else
            ts = trimmed_cls<32, 17, 32>(h, s_nbr, s_norm, n, lo, hi, tid);

        acc = (ts + self0 * (float)(2 * b)) * normd;
    }
    g_accum[node * FDIM + tid] = acc;
}

// ---------------------------------------------------------------------------
// Kernel 2: out = relu(accum @ W + bias)
// Block = 128 threads, tile = 64 rows x 128 cols; 8x8 register tile per
// thread, f32x2-packed accumulators over column pairs, fma.rn.f32x2 inner
// product. W in 64KB dynamic smem; launch_bounds(128,4) caps regs at 128 so
// 4 blocks (16 warps) fit per SM for latency coverage. A is read straight
// from global: 2 distinct addresses per warp load (16-way broadcast via L1).
// ---------------------------------------------------------------------------

#define GT_ROWS 64
#define GEMM_SMEM_BYTES (FDIM * FDIM * 4)   // 64 KB

__device__ __forceinline__ void fma2(ull& d, ull a, ull b) {
    asm("fma.rn.f32x2 %0, %1, %2, %0;" : "+l"(d) : "l"(a), "l"(b));
}
__device__ __forceinline__ ull dup2(float x) {
    ull r;
    asm("mov.b64 %0, {%1, %1};" : "=l"(r) : "f"(x));
    return r;
}
__device__ __forceinline__ void unpack2(float& lo, float& hi, ull v) {
    asm("mov.b64 {%0, %1}, %2;" : "=f"(lo), "=f"(hi) : "l"(v));
}

__global__ __launch_bounds__(128, 4)
void gemm_kernel(const float* __restrict__ W,
                 const float* __restrict__ bias,
                 float* __restrict__ out,
                 int nnode) {
    extern __shared__ float Ws[];      // [128][128], same layout as W

    int tid = threadIdx.x;
    int row0 = blockIdx.x * GT_ROWS;

    // stage W (coalesced float4)
    {
        const float4* Wg = reinterpret_cast<const float4*>(W);
        float4* Wsm = reinterpret_cast<float4*>(Ws);
#pragma unroll
        for (int i = 0; i < FDIM * FDIM / 4 / 128; ++i)
            Wsm[tid + i * 128] = Wg[tid + i * 128];
    }
    __syncthreads();

    int tx = tid & 15;       // column group: cols tx*8 .. tx*8+7
    int ty = tid >> 4;       // row group:    rows ty*8 .. ty*8+7

    ull acc[32];             // acc[r*4+c2] = (row ty*8+r, cols tx*8+2c2..+1)
#pragma unroll
    for (int i = 0; i < 32; ++i) acc[i] = 0ull;

    // per-row A base pointers (clamped for the tail block)
    const float* arow[8];
#pragma unroll
    for (int r = 0; r < 8; ++r) {
        int row = row0 + ty * 8 + r;
        row = row < nnode ? row : nnode - 1;
        arow[r] = g_accum + row * FDIM;
    }

    const ull* wbase = reinterpret_cast<const ull*>(Ws + tx * 8);

#pragma unroll 4
    for (int f2 = 0; f2 < FDIM / 2; ++f2) {
        // A: two f-values per row as one 8B broadcast load
        float2 av[8];
#pragma unroll
        for (int r = 0; r < 8; ++r)
            av[r] = __ldg(reinterpret_cast<const float2*>(arow[r]) + f2);

        // W: column pairs for f and f+1
        ull w0[4], w1[4];
        const ull* wp0 = wbase + (2 * f2) * (FDIM / 2);
        const ull* wp1 = wp0 + (FDIM / 2);
#pragma unroll
        for (int c2 = 0; c2 < 4; ++c2) { w0[c2] = wp0[c2]; w1[c2] = wp1[c2]; }

#pragma unroll
        for (int r = 0; r < 8; ++r) {
            ull a0 = dup2(av[r].x);
            ull a1 = dup2(av[r].y);
#pragma unroll
            for (int c2 = 0; c2 < 4; ++c2) {
                fma2(acc[r * 4 + c2], a0, w0[c2]);
                fma2(acc[r * 4 + c2], a1, w1[c2]);
            }
        }
    }

    // epilogue: bias + relu + store
    float bcol[8];
#pragma unroll
    for (int c = 0; c < 8; ++c) bcol[c] = __ldg(&bias[tx * 8 + c]);

#pragma unroll
    for (int r = 0; r < 8; ++r) {
        int row = row0 + ty * 8 + r;
        if (row < nnode) {
            float* orow = out + row * FDIM + tx * 8;
#pragma unroll
            for (int c2 = 0; c2 < 4; ++c2) {
                float lo, hi;
                unpack2(lo, hi, acc[r * 4 + c2]);
                float2 o;
                o.x = fmaxf(lo + bcol[2 * c2], 0.0f);
                o.y = fmaxf(hi + bcol[2 * c2 + 1], 0.0f);
                *reinterpret_cast<float2*>(orow + 2 * c2) = o;
            }
        }
    }
}

// ---------------------------------------------------------------------------
// launch
// ---------------------------------------------------------------------------

extern "C" void kernel_launch(void* const* d_in, const int* in_sizes, int n_in,
                              void* d_out, int out_size) {
    const float* h    = (const float*)d_in[0];
    const float* norm = (const float*)d_in[1];
    const float* W    = (const float*)d_in[2];
    const float* bias = (const float*)d_in[3];
    const int*   nbr  = (const int*)d_in[4];
    const int*   deg  = (const int*)d_in[5];
    float* out = (float*)d_out;

    int nnode = in_sizes[5];   // 20000

    cudaFuncSetAttribute(gemm_kernel,
                         cudaFuncAttributeMaxDynamicSharedMemorySize,
                         GEMM_SMEM_BYTES);

    agg_kernel<<<nnode, FDIM>>>(h, norm, nbr, deg, nnode);

    int gemm_blocks = (nnode + GT_ROWS - 1) / GT_ROWS;   // 313
    gemm_kernel<<<gemm_blocks, 128, GEMM_SMEM_BYTES>>>(W, bias, out, nnode);
}

// round 6
// speedup vs baseline: 1.7517x; 1.0528x over previous
#include <cuda_runtime.h>
#include <cuda_bf16.h>
#include <math_constants.h>

// ---------------------------------------------------------------------------
// GCNLayer_V2: trimmed-mean neighbor aggregation + linear + bias + relu
//
// Inputs (metadata order):
//   d_in[0] h      float [20000,128]
//   d_in[1] norm   float [20000,1]
//   d_in[2] weight float [128,128]
//   d_in[3] bias   float [128]
//   d_in[4] nbr    int32 [20000,32]
//   d_in[5] deg    int32 [20000]
// Output: float [20000,128] = relu(accum @ W + b)
// ---------------------------------------------------------------------------

#define NNODE 20000
#define NPAD 20032          // padded to a multiple of 64 (tail rows unused)
#define FDIM 128
#define DMAX 32

typedef unsigned long long ull;

// scratch for the aggregated features (device global: no allocation allowed)
__device__ float g_accum[NPAD * FDIM];

// ---------------------------------------------------------------------------
// Compile-time trim bound. Matches runtime floorf(__fmul_rn(n,0.45f)).
// ---------------------------------------------------------------------------
__host__ __device__ constexpr int trim_b(int n) {
    int braw = n / 2 - (1 - (n & 1));
    int bcap = (int)((float)n * 0.45f);
    int b = braw < bcap ? braw : bcap;
    return b < 1 ? 1 : b;
}
// union trim-window over a degree range (for per-class network pruning)
__host__ __device__ constexpr int union_lo(int nmin, int nmax) {
    int m = 1 << 30;
    for (int n = nmin; n <= nmax; ++n) { int v = trim_b(n); if (v < m) m = v; }
    return m;
}
__host__ __device__ constexpr int union_hi(int nmin, int nmax) {
    int M = 0;
    for (int n = nmin; n <= nmax; ++n) { int v = n - trim_b(n); if (v > M) M = v; }
    return M;
}

// ---------------------------------------------------------------------------
// Batcher odd-even merge sort network (pow2), generated at compile time.
// ---------------------------------------------------------------------------
template <int S>
struct OEMSNet {
    int a[200];
    int b[200];
    int count;

    __host__ __device__ constexpr void cmp(int i, int j) {
        a[count] = i; b[count] = j; ++count;
    }
    __host__ __device__ constexpr void merge(int lo, int n, int r) {
        int m = r * 2;
        if (m < n) {
            merge(lo, n, m);
            merge(lo + r, n, m);
            for (int i = lo + r; i + r < lo + n; i += m) cmp(i, i + r);
        } else {
            cmp(lo, lo + r);
        }
    }
    __host__ __device__ constexpr void sort(int lo, int n) {
        if (n > 1) {
            int m = n / 2;
            sort(lo, m);
            sort(lo + m, m);
            merge(lo, n, 1);
        }
    }
    __host__ __device__ constexpr OEMSNet() : a(), b(), count(0) { sort(0, S); }
};

// ---------------------------------------------------------------------------
// Class network: full OEMS<S> pruned by backward liveness so that only CEs
// transitively feeding the union window [ULO, UHI) survive. Valid for any
// runtime n <= S (padded slots hold +inf sentinels; they are ordinary wires).
// ---------------------------------------------------------------------------
template <int S, int ULO, int UHI>
struct ClassNet {
    int a[200];
    int b[200];
    int count;

    __host__ __device__ constexpr ClassNet() : a(), b(), count(0) {
        OEMSNet<S> full{};
        bool live[64] = {};
        for (int i = ULO; i < UHI; ++i) live[i] = true;
        bool keep[200] = {};
        for (int p = full.count - 1; p >= 0; --p) {
            if (live[full.a[p]] || live[full.b[p]]) {
                keep[p] = true;
                live[full.a[p]] = true;
                live[full.b[p]] = true;
            }
        }
        for (int p = 0; p < full.count; ++p)
            if (keep[p]) { a[count] = full.a[p]; b[count] = full.b[p]; ++count; }
    }
};

// ---------------------------------------------------------------------------
// Kernel 1: per-node, per-feature trimmed aggregation.
// Block = 128 threads (one per feature), grid = N nodes. deg is block-uniform
// so the 3-class dispatch is branch-coherent; 3 instantiations keep the hot
// code inside the instruction caches. Each thread sorts (key = h, payload =
// src norm) pairs through the window-pruned network; the window sum fuses
// key*norm via FFMA with the key zero-selected outside [lo,hi) (sentinel keys
// are +inf, so selecting the key, not the payload, avoids inf*0 = NaN).
// ---------------------------------------------------------------------------

template <int S, int NMIN, int NMAX>
__device__ __forceinline__ float trimmed_cls(const float* __restrict__ h,
                                             const int* s_nbr,
                                             const float* s_norm,
                                             int n, int lo, int hi, int tid) {
    constexpr int ULO = union_lo(NMIN, NMAX);
    constexpr int UHI = union_hi(NMIN, NMAX);

    float key[S];
    float val[S];
#pragma unroll
    for (int d = 0; d < S; ++d) {
        if (d < n) {
            int src = s_nbr[d];
            key[d] = __ldg(&h[src * FDIM + tid]);
            val[d] = s_norm[d];
        } else {
            key[d] = CUDART_INF_F;   // sentinel: sorts past all valid
            val[d] = 0.0f;
        }
    }

    constexpr ClassNet<S, ULO, UHI> net{};
#pragma unroll
    for (int p = 0; p < net.count; ++p) {
        const int i = net.a[p];
        const int l = net.b[p];
        float ki = key[i], kl = key[l];
        bool sw = ki > kl;
        key[i] = fminf(ki, kl);       // FMNMX: no predicate dependency
        key[l] = fmaxf(ki, kl);
        float vi = val[i], vl = val[l];
        val[i] = sw ? vl : vi;
        val[l] = sw ? vi : vl;
    }

    // masked fused sum over the union window, ascending rank order
    float ts = 0.0f;
#pragma unroll
    for (int r = ULO; r < UHI; ++r) {
        bool sel = (r >= lo) && (r < hi);
        float kk = sel ? key[r] : 0.0f;    // key zero'd outside window
        ts = fmaf(kk, val[r], ts);
    }
    return ts;
}

__global__ __launch_bounds__(FDIM)
void agg_kernel(const float* __restrict__ h,
                const float* __restrict__ norm,
                const int* __restrict__ nbr,
                const int* __restrict__ deg,
                int nnode) {
    int node = blockIdx.x;
    if (node >= nnode) return;
    int tid = threadIdx.x;

    __shared__ int s_nbr[DMAX];
    __shared__ float s_norm[DMAX];
    __shared__ int s_n;
    __shared__ float s_nd;

    if (tid < DMAX) {
        int src = nbr[node * DMAX + tid];
        s_nbr[tid] = src;
        s_norm[tid] = norm[src];
    }
    if (tid == 0) {
        s_n = deg[node];
        s_nd = norm[node];
    }
    __syncthreads();

    int n = s_n;                 // block-uniform
    float normd = s_nd;
    float self0 = h[node * FDIM + tid] * normd;

    float acc;
    if (n <= 3) {
        acc = ((float)n * self0) * normd;
    } else {
        int braw = (n >> 1) - (1 - (n & 1));
        int bcap = (int)floorf(__fmul_rn((float)n, 0.45f));
        int b = min(braw, bcap);
        b = max(b, 1);
        int lo = b, hi = n - b;

        float ts;
        if (n <= 8)
            ts = trimmed_cls<8, 4, 8>(h, s_nbr, s_norm, n, lo, hi, tid);
        else if (n <= 16)
            ts = trimmed_cls<16, 9, 16>(h, s_nbr, s_norm, n, lo, hi, tid);
        else
            ts = trimmed_cls<32, 17, 32>(h, s_nbr, s_norm, n, lo, hi, tid);

        acc = (ts + self0 * (float)(2 * b)) * normd;
    }
    g_accum[node * FDIM + tid] = acc;
}

// ---------------------------------------------------------------------------
// Kernel 2: out = relu(accum @ W + bias)
// Tile = 64 rows x 64 cols, 128 threads, 8x4 register tile per thread.
// Grid = 313 row-tiles x 2 col-halves = 626 blocks (~4.2/SM) so residency is
// grid-fed, not smem-capped: W half in 32KB smem -> smem cap 7, regs ~<102
// via launch_bounds(128,5). g_accum is padded to 20032 rows so A loads use a
// single base pointer with immediate offsets (no clamping, no pointer array).
// f32x2-packed accumulators + fma.rn.f32x2.
// ---------------------------------------------------------------------------

#define GT_ROWS 64
#define GT_COLS 64
#define GEMM_SMEM_BYTES (FDIM * GT_COLS * 4)   // 32 KB

__device__ __forceinline__ void fma2(ull& d, ull a, ull b) {
    asm("fma.rn.f32x2 %0, %1, %2, %0;" : "+l"(d) : "l"(a), "l"(b));
}
__device__ __forceinline__ ull dup2(float x) {
    ull r;
    asm("mov.b64 %0, {%1, %1};" : "=l"(r) : "f"(x));
    return r;
}
__device__ __forceinline__ void unpack2(float& lo, float& hi, ull v) {
    asm("mov.b64 {%0, %1}, %2;" : "=f"(lo), "=f"(hi) : "l"(v));
}

__global__ __launch_bounds__(128, 5)
void gemm_kernel(const float* __restrict__ W,
                 const float* __restrict__ bias,
                 float* __restrict__ out,
                 int nnode) {
    extern __shared__ float Ws[];      // [128][64] : W rows, this block's col half

    int tid = threadIdx.x;
    int row0 = (blockIdx.x >> 1) * GT_ROWS;
    int col0 = (blockIdx.x & 1) * GT_COLS;

    // stage this column half of W (coalesced float4: 16 float4 per W row)
    {
#pragma unroll
        for (int i = 0; i < FDIM * GT_COLS / 4 / 128; ++i) {
            int idx = tid + i * 128;
            int f = idx >> 4;          // W row
            int c4 = idx & 15;         // float4 within the half-row
            *reinterpret_cast<float4*>(Ws + f * GT_COLS + c4 * 4) =
                *reinterpret_cast<const float4*>(W + f * FDIM + col0 + c4 * 4);
        }
    }
    __syncthreads();

    int tx = tid & 15;       // column group: cols col0 + tx*4 .. +3
    int ty = tid >> 4;       // row group:    rows row0 + ty*8 .. +7

    ull acc[16];             // acc[r*2+c2] = (row ty*8+r, cols tx*4+2c2..+1)
#pragma unroll
    for (int i = 0; i < 16; ++i) acc[i] = 0ull;

    const float* abase = g_accum + (row0 + ty * 8) * FDIM;   // padded: no clamp
    const ull* wbase = reinterpret_cast<const ull*>(Ws + tx * 4);

#pragma unroll 4
    for (int f2 = 0; f2 < FDIM / 2; ++f2) {
        // A: two f-values per row as one 8B broadcast load (immediate offsets)
        float2 av[8];
#pragma unroll
        for (int r = 0; r < 8; ++r)
            av[r] = __ldg(reinterpret_cast<const float2*>(abase + r * FDIM) + f2);

        // W: column pairs for f and f+1
        ull w0[2], w1[2];
        const ull* wp0 = wbase + (2 * f2) * (GT_COLS / 2);
        const ull* wp1 = wp0 + (GT_COLS / 2);
        w0[0] = wp0[0]; w0[1] = wp0[1];
        w1[0] = wp1[0]; w1[1] = wp1[1];

#pragma unroll
        for (int r = 0; r < 8; ++r) {
            ull a0 = dup2(av[r].x);
            ull a1 = dup2(av[r].y);
#pragma unroll
            for (int c2 = 0; c2 < 2; ++c2) {
                fma2(acc[r * 2 + c2], a0, w0[c2]);
                fma2(acc[r * 2 + c2], a1, w1[c2]);
            }
        }
    }

    // epilogue: bias + relu + store
    float bcol[4];
#pragma unroll
    for (int c = 0; c < 4; ++c) bcol[c] = __ldg(&bias[col0 + tx * 4 + c]);

#pragma unroll
    for (int r = 0; r < 8; ++r) {
        int row = row0 + ty * 8 + r;
        if (row < nnode) {
            float* orow = out + row * FDIM + col0 + tx * 4;
#pragma unroll
            for (int c2 = 0; c2 < 2; ++c2) {
                float lo, hi;
                unpack2(lo, hi, acc[r * 2 + c2]);
                float2 o;
                o.x = fmaxf(lo + bcol[2 * c2], 0.0f);
                o.y = fmaxf(hi + bcol[2 * c2 + 1], 0.0f);
                *reinterpret_cast<float2*>(orow + 2 * c2) = o;
            }
        }
    }
}

// ---------------------------------------------------------------------------
// launch
// ---------------------------------------------------------------------------

extern "C" void kernel_launch(void* const* d_in, const int* in_sizes, int n_in,
                              void* d_out, int out_size) {
    const float* h    = (const float*)d_in[0];
    const float* norm = (const float*)d_in[1];
    const float* W    = (const float*)d_in[2];
    const float* bias = (const float*)d_in[3];
    const int*   nbr  = (const int*)d_in[4];
    const int*   deg  = (const int*)d_in[5];
    float* out = (float*)d_out;

    int nnode = in_sizes[5];   // 20000

    cudaFuncSetAttribute(gemm_kernel,
                         cudaFuncAttributeMaxDynamicSharedMemorySize,
                         GEMM_SMEM_BYTES);

    agg_kernel<<<nnode, FDIM>>>(h, norm, nbr, deg, nnode);

    int row_tiles = (NPAD / GT_ROWS);                 // 313
    gemm_kernel<<<row_tiles * 2, 128, GEMM_SMEM_BYTES>>>(W, bias, out, nnode);
}